// round 1
// baseline (speedup 1.0000x reference)
#include <cuda_runtime.h>

#define NN 50000
#define EE 800000
#define HH 64
#define PP 20
#define GG 500

// ---------------- device scratch (static allocations are allowed) ----------
__device__ float g_pe[NN * HH];
__device__ float g_h[NN * HH];
__device__ float g_tmp[NN * HH];
__device__ float g_dinv[NN];
__device__ int   g_deg[NN];
__device__ int   g_offs[NN + 1];
__device__ int   g_cursor[NN];
__device__ int   g_csr[EE];
__device__ int   g_bsum[64];
__device__ int   g_bscan[64];
__device__ float g_bnsum[HH], g_bnsum2[HH], g_scale[HH], g_shift[HH];

// ---------------- CSR build ------------------------------------------------
__global__ void k_zero() {
    int i = blockIdx.x * blockDim.x + threadIdx.x;
    if (i < NN) g_deg[i] = 0;
    if (i < HH) { g_bnsum[i] = 0.f; g_bnsum2[i] = 0.f; }
}

__global__ void k_deg(const int* __restrict__ dst) {
    int i = blockIdx.x * blockDim.x + threadIdx.x;
    if (i < EE) atomicAdd(&g_deg[dst[i]], 1);
}

__global__ void k_scan_part() {
    __shared__ int sh[1024];
    int t = threadIdx.x;
    int i = blockIdx.x * 1024 + t;
    sh[t] = (i < NN) ? g_deg[i] : 0;
    __syncthreads();
    for (int s = 512; s > 0; s >>= 1) {
        if (t < s) sh[t] += sh[t + s];
        __syncthreads();
    }
    if (t == 0) g_bsum[blockIdx.x] = sh[0];
}

__global__ void k_scan_mid(int nb) {
    __shared__ int sh[64];
    int t = threadIdx.x;
    int v = (t < nb) ? g_bsum[t] : 0;
    sh[t] = v;
    __syncthreads();
    for (int d = 1; d < 64; d <<= 1) {
        int x = (t >= d) ? sh[t - d] : 0;
        __syncthreads();
        sh[t] += x;
        __syncthreads();
    }
    g_bscan[t] = sh[t] - v;  // exclusive
}

__global__ void k_scan_final() {
    __shared__ int sh[1024];
    int t = threadIdx.x;
    int i = blockIdx.x * 1024 + t;
    int v = (i < NN) ? g_deg[i] : 0;
    sh[t] = v;
    __syncthreads();
    for (int d = 1; d < 1024; d <<= 1) {
        int x = (t >= d) ? sh[t - d] : 0;
        __syncthreads();
        sh[t] += x;
        __syncthreads();
    }
    int excl = sh[t] - v + g_bscan[blockIdx.x];
    if (i < NN) {
        g_offs[i] = excl;
        g_cursor[i] = excl;
        g_dinv[i] = rsqrtf((float)v + 1.0f);
        if (i == NN - 1) g_offs[NN] = excl + v;
    }
}

__global__ void k_scatter(const int* __restrict__ src, const int* __restrict__ dst) {
    int i = blockIdx.x * blockDim.x + threadIdx.x;
    if (i >= EE) return;
    int d = dst[i];
    int pos = atomicAdd(&g_cursor[d], 1);
    g_csr[pos] = src[i];
}

// ---------------- dense GEMM: out = act_in @ W (K x 64) --------------------
// act_in = A (+ A2 if ADD2).  epilogue: (+bias if BIAS) then (*dinv[row] if SCALE)
template <int K, bool ADD2, bool SCALE, bool BIAS>
__global__ void k_gemm(const float* __restrict__ A, const float* __restrict__ A2,
                       const float* __restrict__ W, const float* __restrict__ bias,
                       float* __restrict__ out, int n) {
    __shared__ __align__(16) float in_s[64][K];
    __shared__ __align__(16) float wt_s[64][K];  // W transposed: wt_s[j][k]
    int tid = threadIdx.x;                       // 256 threads
    int row0 = blockIdx.x * 64;

    for (int i = tid; i < 64 * K; i += 256) {
        int k = i / 64, j = i % 64;
        wt_s[j][k] = W[i];
    }
    constexpr int NV = 64 * K / 4;
    const float4* A4  = (const float4*)A;
    const float4* A24 = (const float4*)A2;
    for (int i = tid; i < NV; i += 256) {
        int r = i / (K / 4), c = i % (K / 4);
        int row = row0 + r;
        float4 v = make_float4(0.f, 0.f, 0.f, 0.f);
        if (row < n) {
            v = A4[row * (K / 4) + c];
            if (ADD2) {
                float4 w = A24[row * (K / 4) + c];
                v.x += w.x; v.y += w.y; v.z += w.z; v.w += w.w;
            }
        }
        *(((float4*)in_s[r]) + c) = v;
    }
    __syncthreads();

    int tx = tid & 15, ty = tid >> 4;
    float acc[4][4];
#pragma unroll
    for (int i = 0; i < 4; i++)
#pragma unroll
        for (int j = 0; j < 4; j++) acc[i][j] = 0.f;

    for (int k = 0; k < K; k += 4) {
        float4 a[4], b[4];
#pragma unroll
        for (int i = 0; i < 4; i++) a[i] = *(const float4*)&in_s[ty * 4 + i][k];
#pragma unroll
        for (int j = 0; j < 4; j++) b[j] = *(const float4*)&wt_s[tx * 4 + j][k];
#pragma unroll
        for (int i = 0; i < 4; i++)
#pragma unroll
            for (int j = 0; j < 4; j++)
                acc[i][j] += a[i].x * b[j].x + a[i].y * b[j].y + a[i].z * b[j].z + a[i].w * b[j].w;
    }

#pragma unroll
    for (int i = 0; i < 4; i++) {
        int row = row0 + ty * 4 + i;
        if (row >= n) continue;
        float s = SCALE ? g_dinv[row] : 1.0f;
        float o[4];
#pragma unroll
        for (int j = 0; j < 4; j++) {
            float v = acc[i][j];
            if (BIAS) v += bias[tx * 4 + j];
            o[j] = v * s;
        }
        *(float4*)&out[row * 64 + tx * 4] = make_float4(o[0], o[1], o[2], o[3]);
    }
}

// ---------------- sparse aggregation (pull via CSR, warp per node) ---------
// out[d] = relu?( (sum_{src in N(d)} tmp[src] + tmp[d]) * dinv[d] + bias )
__global__ void k_aggr(const float* __restrict__ tmp, const float* __restrict__ bias,
                       float* __restrict__ out, int relu) {
    int wid = (blockIdx.x * blockDim.x + threadIdx.x) >> 5;
    int lane = threadIdx.x & 31;
    if (wid >= NN) return;
    int beg = g_offs[wid], end = g_offs[wid + 1];
    const float2* t2 = (const float2*)tmp;
    float2 acc = t2[wid * 32 + lane];  // self-loop term (tmp already *dinv[row])
    int e = beg;
    for (; e + 4 <= end; e += 4) {
        int s0 = g_csr[e], s1 = g_csr[e + 1], s2 = g_csr[e + 2], s3 = g_csr[e + 3];
        float2 v0 = t2[s0 * 32 + lane];
        float2 v1 = t2[s1 * 32 + lane];
        float2 v2 = t2[s2 * 32 + lane];
        float2 v3 = t2[s3 * 32 + lane];
        acc.x += (v0.x + v1.x) + (v2.x + v3.x);
        acc.y += (v0.y + v1.y) + (v2.y + v3.y);
    }
    for (; e < end; e++) {
        int s = g_csr[e];
        float2 v = t2[s * 32 + lane];
        acc.x += v.x; acc.y += v.y;
    }
    float d = g_dinv[wid];
    float2 bv = ((const float2*)bias)[lane];
    float ox = acc.x * d + bv.x;
    float oy = acc.y * d + bv.y;
    if (relu) { ox = fmaxf(ox, 0.f); oy = fmaxf(oy, 0.f); }
    ((float2*)out)[wid * 32 + lane] = make_float2(ox, oy);
}

// ---------------- BatchNorm stats + pool -----------------------------------
__global__ void k_bn_stats(const float* __restrict__ h) {
    int t = threadIdx.x;
    int col = t & 63, sub = t >> 6;
    float s = 0.f, s2 = 0.f;
    for (int r = blockIdx.x * 4 + sub; r < NN; r += gridDim.x * 4) {
        float v = h[r * 64 + col];
        s += v; s2 += v * v;
    }
    __shared__ float sh[4][64], sh2[4][64];
    sh[sub][col] = s; sh2[sub][col] = s2;
    __syncthreads();
    if (sub == 0) {
        float ts = sh[0][col] + sh[1][col] + sh[2][col] + sh[3][col];
        float t2 = sh2[0][col] + sh2[1][col] + sh2[2][col] + sh2[3][col];
        atomicAdd(&g_bnsum[col], ts);
        atomicAdd(&g_bnsum2[col], t2);
    }
}

__global__ void k_bn_final(const float* __restrict__ gamma, const float* __restrict__ beta) {
    int c = threadIdx.x;
    float mu = g_bnsum[c] / (float)NN;
    float var = g_bnsum2[c] / (float)NN - mu * mu;
    float r = rsqrtf(var + 1e-5f);
    float sc = r * gamma[c];
    g_scale[c] = sc;
    g_shift[c] = beta[c] - mu * sc;
}

__global__ void k_pool(const float* __restrict__ h, const int* __restrict__ ptr,
                       float* __restrict__ out) {
    int g = blockIdx.x;
    int beg = ptr[g], end = ptr[g + 1];
    int t = threadIdx.x;
    int col = t & 63, sub = t >> 6;
    float acc = 0.f;
    for (int r = beg + sub; r < end; r += 4) {
        float v = h[r * 64 + col] * g_scale[col] + g_shift[col];
        acc += fmaxf(v, 0.f);
    }
    __shared__ float sh[4][64];
    sh[sub][col] = acc;
    __syncthreads();
    if (sub == 0) {
        float s = sh[0][col] + sh[1][col] + sh[2][col] + sh[3][col];
        out[g * 64 + col] = s / (float)(end - beg);
    }
}

// ---------------- launch ----------------------------------------------------
extern "C" void kernel_launch(void* const* d_in, const int* in_sizes, int n_in,
                              void* d_out, int out_size) {
    const float* x     = (const float*)d_in[0];
    const float* rwpe  = (const float*)d_in[1];
    const float* W_rw  = (const float*)d_in[2];
    const float* b_rw  = (const float*)d_in[3];
    const float *Wc[5], *bc[5], *Wp[5], *bp[5];
    for (int i = 0; i < 5; i++) {
        Wc[i] = (const float*)d_in[4 + 4 * i];
        bc[i] = (const float*)d_in[5 + 4 * i];
        Wp[i] = (const float*)d_in[6 + 4 * i];
        bp[i] = (const float*)d_in[7 + 4 * i];
    }
    const float* gamma = (const float*)d_in[24];
    const float* beta  = (const float*)d_in[25];
    const int*   ei    = (const int*)d_in[26];
    const int*   ptr   = (const int*)d_in[27];
    float*       out   = (float*)d_out;
    const int* src = ei;
    const int* dst = ei + EE;

    float *pe, *h, *tmp;
    cudaGetSymbolAddress((void**)&pe, g_pe);
    cudaGetSymbolAddress((void**)&h, g_h);
    cudaGetSymbolAddress((void**)&tmp, g_tmp);

    const int GEMM_GRID = (NN + 63) / 64;   // 782
    const int AGGR_GRID = (NN * 32 + 255) / 256;  // 6250

    // CSR build (per-call: deterministic same-work)
    k_zero<<<(NN + 255) / 256, 256>>>();
    k_deg<<<(EE + 255) / 256, 256>>>(dst);
    k_scan_part<<<49, 1024>>>();
    k_scan_mid<<<1, 64>>>(49);
    k_scan_final<<<49, 1024>>>();
    k_scatter<<<(EE + 255) / 256, 256>>>(src, dst);

    // pe0 = RWPE @ W_rw + b_rw
    k_gemm<PP, false, false, true><<<GEMM_GRID, 256>>>(rwpe, nullptr, W_rw, b_rw, pe, NN);

    // h = relu(conv(x + pe, Wc1, bc1))
    k_gemm<64, true, true, false><<<GEMM_GRID, 256>>>(x, pe, Wc[0], nullptr, tmp, NN);
    k_aggr<<<AGGR_GRID, 256>>>(tmp, bc[0], h, 1);

    for (int k = 0; k < 4; k++) {
        // pe = relu(conv(pe, Wp_{k+1}, bp_{k+1}))
        k_gemm<64, false, true, false><<<GEMM_GRID, 256>>>(pe, nullptr, Wp[k], nullptr, tmp, NN);
        k_aggr<<<AGGR_GRID, 256>>>(tmp, bp[k], pe, 1);
        // h = conv(h + pe, Wc_{k+2}, bc_{k+2}); relu except the last
        k_gemm<64, true, true, false><<<GEMM_GRID, 256>>>(h, pe, Wc[k + 1], nullptr, tmp, NN);
        k_aggr<<<AGGR_GRID, 256>>>(tmp, bc[k + 1], h, (k < 3) ? 1 : 0);
    }

    // BatchNorm (training stats) + relu + mean-pool per graph
    k_bn_stats<<<128, 256>>>(h);
    k_bn_final<<<1, 64>>>(gamma, beta);
    k_pool<<<GG, 256>>>(h, ptr, out);
}

// round 2
// speedup vs baseline: 2.3208x; 2.3208x over previous
#include <cuda_runtime.h>
#include <cuda_bf16.h>

#define NN 50000
#define EE 800000
#define HH 64
#define PP 20
#define GG 500

// ---------------- device scratch ----------
__device__ float          g_pe[NN * HH];
__device__ float          g_h[NN * HH];
__device__ __nv_bfloat162 g_tmp[NN * (HH / 2)];   // bf16 messages, 128B/row
__device__ float g_dinv[NN];
__device__ int   g_deg[NN];
__device__ int   g_offs[NN + 1];
__device__ int   g_cursor[NN];
__device__ int   g_csr[EE];
__device__ int   g_bsum[64];
__device__ float g_bnsum[HH], g_bnsum2[HH];

// ---------------- CSR build ------------------------------------------------
__global__ void k_zero() {
    int i = blockIdx.x * blockDim.x + threadIdx.x;
    if (i < NN) g_deg[i] = 0;
    if (i < HH) { g_bnsum[i] = 0.f; g_bnsum2[i] = 0.f; }
}

__global__ void k_deg(const int* __restrict__ dst) {
    int i = blockIdx.x * blockDim.x + threadIdx.x;
    if (i < EE) atomicAdd(&g_deg[dst[i]], 1);
}

__global__ void k_scan_part() {
    __shared__ int sh[1024];
    int t = threadIdx.x;
    int i = blockIdx.x * 1024 + t;
    sh[t] = (i < NN) ? g_deg[i] : 0;
    __syncthreads();
    for (int s = 512; s > 0; s >>= 1) {
        if (t < s) sh[t] += sh[t + s];
        __syncthreads();
    }
    if (t == 0) g_bsum[blockIdx.x] = sh[0];
}

// merged: local exclusive scan of the 49 block sums + full block scan
__global__ void k_scan_final() {
    __shared__ int bs[64];
    __shared__ int sh[1024];
    int t = threadIdx.x;
    if (t < 64) bs[t] = (t < 49) ? g_bsum[t] : 0;
    __syncthreads();
    if (t == 0) {
        int run = 0;
        for (int i = 0; i < 49; i++) { int v = bs[i]; bs[i] = run; run += v; }
    }
    int i = blockIdx.x * 1024 + t;
    int v = (i < NN) ? g_deg[i] : 0;
    sh[t] = v;
    __syncthreads();
    for (int d = 1; d < 1024; d <<= 1) {
        int x = (t >= d) ? sh[t - d] : 0;
        __syncthreads();
        sh[t] += x;
        __syncthreads();
    }
    int excl = sh[t] - v + bs[blockIdx.x];
    if (i < NN) {
        g_offs[i] = excl;
        g_cursor[i] = excl;
        g_dinv[i] = rsqrtf((float)v + 1.0f);
        if (i == NN - 1) g_offs[NN] = excl + v;
    }
}

__global__ void k_scatter(const int* __restrict__ src, const int* __restrict__ dst) {
    int i = blockIdx.x * blockDim.x + threadIdx.x;
    if (i >= EE) return;
    int d = dst[i];
    int pos = atomicAdd(&g_cursor[d], 1);
    g_csr[pos] = src[i];
}

// ---------------- dense GEMM: out = act_in @ W (K x 64) --------------------
// wt_s stored k-major (W's native layout) -> conflict-free b loads.
// epilogue: (+bias if BIAS) then (*dinv[row] if SCALE); bf16 out if BF16OUT.
template <int K, bool ADD2, bool SCALE, bool BIAS, bool BF16OUT>
__global__ void k_gemm(const float* __restrict__ A, const float* __restrict__ A2,
                       const float* __restrict__ W, const float* __restrict__ bias,
                       void* __restrict__ out, int n) {
    __shared__ __align__(16) float in_s[64][K];
    __shared__ __align__(16) float wt_s[K][64];
    int tid = threadIdx.x;                       // 256 threads
    int row0 = blockIdx.x * 64;

    // stage W: native layout copy, coalesced + conflict-free
    {
        const float4* W4 = (const float4*)W;
        float4* ws4 = (float4*)&wt_s[0][0];
        for (int i = tid; i < K * 64 / 4; i += 256) ws4[i] = W4[i];
    }
    // stage A (+A2)
    {
        constexpr int RV = K / 4;                // float4 per row
        const float4* A4  = (const float4*)A;
        const float4* A24 = (const float4*)A2;
        for (int i = tid; i < 64 * RV; i += 256) {
            int r = i / RV, c = i % RV;
            int row = row0 + r;
            float4 v = make_float4(0.f, 0.f, 0.f, 0.f);
            if (row < n) {
                v = A4[row * RV + c];
                if (ADD2) {
                    float4 w = A24[row * RV + c];
                    v.x += w.x; v.y += w.y; v.z += w.z; v.w += w.w;
                }
            }
            *(((float4*)in_s[r]) + c) = v;
        }
    }
    __syncthreads();

    int tx = tid & 15, ty = tid >> 4;
    float acc[4][4];
#pragma unroll
    for (int i = 0; i < 4; i++)
#pragma unroll
        for (int j = 0; j < 4; j++) acc[i][j] = 0.f;

#pragma unroll
    for (int k = 0; k < K; k += 4) {
        float4 a[4], b[4];
#pragma unroll
        for (int i = 0; i < 4; i++) a[i] = *(const float4*)&in_s[ty * 4 + i][k];
#pragma unroll
        for (int kk = 0; kk < 4; kk++) b[kk] = *(const float4*)&wt_s[k + kk][tx * 4];
#pragma unroll
        for (int i = 0; i < 4; i++) {
            acc[i][0] += a[i].x * b[0].x + a[i].y * b[1].x + a[i].z * b[2].x + a[i].w * b[3].x;
            acc[i][1] += a[i].x * b[0].y + a[i].y * b[1].y + a[i].z * b[2].y + a[i].w * b[3].y;
            acc[i][2] += a[i].x * b[0].z + a[i].y * b[1].z + a[i].z * b[2].z + a[i].w * b[3].z;
            acc[i][3] += a[i].x * b[0].w + a[i].y * b[1].w + a[i].z * b[2].w + a[i].w * b[3].w;
        }
    }

#pragma unroll
    for (int i = 0; i < 4; i++) {
        int row = row0 + ty * 4 + i;
        if (row >= n) continue;
        float s = SCALE ? g_dinv[row] : 1.0f;
        float o[4];
#pragma unroll
        for (int j = 0; j < 4; j++) {
            float v = acc[i][j];
            if (BIAS) v += bias[tx * 4 + j];
            o[j] = v * s;
        }
        if (BF16OUT) {
            __nv_bfloat162 p0 = __floats2bfloat162_rn(o[0], o[1]);
            __nv_bfloat162 p1 = __floats2bfloat162_rn(o[2], o[3]);
            uint2 pk;
            pk.x = *(unsigned int*)&p0;
            pk.y = *(unsigned int*)&p1;
            ((uint2*)out)[row * 16 + tx] = pk;
        } else {
            *(float4*)&((float*)out)[row * 64 + tx * 4] = make_float4(o[0], o[1], o[2], o[3]);
        }
    }
}

// ---------------- sparse aggregation (pull via CSR, warp per node) ---------
// out[d] = relu?( (sum_{src in N(d)} tmp[src] + tmp[d]) * dinv[d] + bias )
__global__ void k_aggr(const __nv_bfloat162* __restrict__ t2, const float* __restrict__ bias,
                       float* __restrict__ out, int relu) {
    int wid = (blockIdx.x * blockDim.x + threadIdx.x) >> 5;
    int lane = threadIdx.x & 31;
    if (wid >= NN) return;
    int beg = g_offs[wid], end = g_offs[wid + 1];
    float2 acc = __bfloat1622float2(t2[wid * 32 + lane]);  // self term (already *dinv)
    int e = beg;
    for (; e + 4 <= end; e += 4) {
        int s0 = g_csr[e], s1 = g_csr[e + 1], s2 = g_csr[e + 2], s3 = g_csr[e + 3];
        float2 v0 = __bfloat1622float2(t2[s0 * 32 + lane]);
        float2 v1 = __bfloat1622float2(t2[s1 * 32 + lane]);
        float2 v2 = __bfloat1622float2(t2[s2 * 32 + lane]);
        float2 v3 = __bfloat1622float2(t2[s3 * 32 + lane]);
        acc.x += (v0.x + v1.x) + (v2.x + v3.x);
        acc.y += (v0.y + v1.y) + (v2.y + v3.y);
    }
    for (; e < end; e++) {
        int s = g_csr[e];
        float2 v = __bfloat1622float2(t2[s * 32 + lane]);
        acc.x += v.x; acc.y += v.y;
    }
    float d = g_dinv[wid];
    float2 bv = ((const float2*)bias)[lane];
    float ox = acc.x * d + bv.x;
    float oy = acc.y * d + bv.y;
    if (relu) { ox = fmaxf(ox, 0.f); oy = fmaxf(oy, 0.f); }
    ((float2*)out)[wid * 32 + lane] = make_float2(ox, oy);
}

// ---------------- BatchNorm stats + fused norm/relu/pool -------------------
__global__ void k_bn_stats(const float* __restrict__ h) {
    int t = threadIdx.x;
    int col = t & 63, sub = t >> 6;
    float s = 0.f, s2 = 0.f;
    for (int r = blockIdx.x * 4 + sub; r < NN; r += gridDim.x * 4) {
        float v = h[r * 64 + col];
        s += v; s2 += v * v;
    }
    __shared__ float sh[4][64], sh2[4][64];
    sh[sub][col] = s; sh2[sub][col] = s2;
    __syncthreads();
    if (sub == 0) {
        float ts = sh[0][col] + sh[1][col] + sh[2][col] + sh[3][col];
        float t2 = sh2[0][col] + sh2[1][col] + sh2[2][col] + sh2[3][col];
        atomicAdd(&g_bnsum[col], ts);
        atomicAdd(&g_bnsum2[col], t2);
    }
}

__global__ void k_pool(const float* __restrict__ h, const int* __restrict__ ptr,
                       const float* __restrict__ gamma, const float* __restrict__ beta,
                       float* __restrict__ out) {
    __shared__ float sscale[64], sshift[64];
    int t = threadIdx.x;
    if (t < 64) {
        float mu = g_bnsum[t] / (float)NN;
        float var = g_bnsum2[t] / (float)NN - mu * mu;
        float r = rsqrtf(var + 1e-5f);
        float sc = r * gamma[t];
        sscale[t] = sc;
        sshift[t] = beta[t] - mu * sc;
    }
    __syncthreads();
    int g = blockIdx.x;
    int beg = ptr[g], end = ptr[g + 1];
    int col = t & 63, sub = t >> 6;
    float acc = 0.f;
    for (int r = beg + sub; r < end; r += 4) {
        float v = h[r * 64 + col] * sscale[col] + sshift[col];
        acc += fmaxf(v, 0.f);
    }
    __shared__ float sh[4][64];
    sh[sub][col] = acc;
    __syncthreads();
    if (sub == 0) {
        float s = sh[0][col] + sh[1][col] + sh[2][col] + sh[3][col];
        out[g * 64 + col] = s / (float)(end - beg);
    }
}

// ---------------- launch ----------------------------------------------------
extern "C" void kernel_launch(void* const* d_in, const int* in_sizes, int n_in,
                              void* d_out, int out_size) {
    const float* x     = (const float*)d_in[0];
    const float* rwpe  = (const float*)d_in[1];
    const float* W_rw  = (const float*)d_in[2];
    const float* b_rw  = (const float*)d_in[3];
    const float *Wc[5], *bc[5], *Wp[5], *bp[5];
    for (int i = 0; i < 5; i++) {
        Wc[i] = (const float*)d_in[4 + 4 * i];
        bc[i] = (const float*)d_in[5 + 4 * i];
        Wp[i] = (const float*)d_in[6 + 4 * i];
        bp[i] = (const float*)d_in[7 + 4 * i];
    }
    const float* gamma = (const float*)d_in[24];
    const float* beta  = (const float*)d_in[25];
    const int*   ei    = (const int*)d_in[26];
    const int*   ptr   = (const int*)d_in[27];
    float*       out   = (float*)d_out;
    const int* src = ei;
    const int* dst = ei + EE;

    float *pe, *h;
    __nv_bfloat162* tmp;
    cudaGetSymbolAddress((void**)&pe, g_pe);
    cudaGetSymbolAddress((void**)&h, g_h);
    cudaGetSymbolAddress((void**)&tmp, g_tmp);

    const int GEMM_GRID = (NN + 63) / 64;          // 782
    const int AGGR_GRID = (NN * 32 + 255) / 256;   // 6250

    // CSR build
    k_zero<<<(NN + 255) / 256, 256>>>();
    k_deg<<<(EE + 255) / 256, 256>>>(dst);
    k_scan_part<<<49, 1024>>>();
    k_scan_final<<<49, 1024>>>();
    k_scatter<<<(EE + 255) / 256, 256>>>(src, dst);

    // pe0 = RWPE @ W_rw + b_rw   (fp32 out; 6th launch -> ncu target)
    k_gemm<PP, false, false, true, false><<<GEMM_GRID, 256>>>(rwpe, nullptr, W_rw, b_rw, pe, NN);

    // h = relu(conv(x + pe, Wc1, bc1))
    k_gemm<64, true, true, false, true><<<GEMM_GRID, 256>>>(x, pe, Wc[0], nullptr, tmp, NN);
    k_aggr<<<AGGR_GRID, 256>>>(tmp, bc[0], h, 1);

    for (int k = 0; k < 4; k++) {
        // pe = relu(conv(pe, Wp_{k+1}, bp_{k+1}))
        k_gemm<64, false, true, false, true><<<GEMM_GRID, 256>>>(pe, nullptr, Wp[k], nullptr, tmp, NN);
        k_aggr<<<AGGR_GRID, 256>>>(tmp, bp[k], pe, 1);
        // h = conv(h + pe, Wc_{k+2}, bc_{k+2}); relu except last
        k_gemm<64, true, true, false, true><<<GEMM_GRID, 256>>>(h, pe, Wc[k + 1], nullptr, tmp, NN);
        k_aggr<<<AGGR_GRID, 256>>>(tmp, bc[k + 1], h, (k < 3) ? 1 : 0);
    }

    // BatchNorm (training stats) + relu + mean-pool per graph
    k_bn_stats<<<128, 256>>>(h);
    k_pool<<<GG, 256>>>(h, ptr, gamma, beta, out);
}